// round 1
// baseline (speedup 1.0000x reference)
#include <cuda_runtime.h>

// CapsuleLayer dynamic routing, GB300 sm_103a
// inputs: [B, I, K] fp32 ; W: [J, I, D, K] fp32 ; out: [B, J, D] fp32
#define BB 256
#define II 2048
#define KK 8
#define JJ 10
#define DD 16
#define NCHUNK 4
#define ICHUNK (II / NCHUNK)   // 512

// Scratch (device globals only; no allocation allowed)
__device__ float g_uhat[(size_t)BB * JJ * II * DD];  // [b][j][i][d]  335.5 MB
__device__ float g_s[BB * JJ * DD];                  // routing weighted sum
__device__ float g_osum[BB * JJ * DD];               // running sum of squashed outputs

// ---------------------------------------------------------------------------
__global__ void init_kernel() {
    int t = blockIdx.x * blockDim.x + threadIdx.x;
    if (t < BB * JJ * DD) {
        g_s[t] = 0.0f;
        g_osum[t] = 0.0f;
    }
}

// ---------------------------------------------------------------------------
// u_hat[b,j,i,d] = sum_k W[j,i,d,k] * in[b,i,k]
// Grid: one CTA per i (2048 CTAs). 640 threads = 16 bl x 10 j x 4 dq.
// Each thread keeps W[j,i, dq*4..dq*4+3, 0..7] (32 floats) in registers and
// loops over 16 batch tiles, so W is read once per CTA.
__global__ __launch_bounds__(640, 2)
void uhat_kernel(const float* __restrict__ inp, const float* __restrict__ W) {
    const int i = blockIdx.x;
    __shared__ float in_s[BB][KK];   // 8 KB: inputs[:, i, :]

    const int tid = threadIdx.x;
    // Stage inputs for this i: 2048 floats = 512 float4
    for (int t = tid; t < (BB * KK) / 4; t += 640) {
        int b = t >> 1, kq = t & 1;
        *(float4*)&in_s[b][kq * 4] =
            *(const float4*)&inp[((size_t)b * II + i) * KK + kq * 4];
    }

    const int bl = tid / 40;
    const int rem = tid % 40;
    const int j = rem >> 2;
    const int dq = rem & 3;

    float w[32];
    {
        const float* wp = W + (((size_t)j * II + i) * DD + dq * 4) * KK;
#pragma unroll
        for (int q = 0; q < 8; q++) {
            float4 v = *(const float4*)(wp + q * 4);
            w[q * 4 + 0] = v.x; w[q * 4 + 1] = v.y;
            w[q * 4 + 2] = v.z; w[q * 4 + 3] = v.w;
        }
    }
    __syncthreads();

#pragma unroll 4
    for (int bo = 0; bo < 16; bo++) {
        int b = bo * 16 + bl;
        float4 a0 = *(const float4*)&in_s[b][0];
        float4 a1 = *(const float4*)&in_s[b][4];
        float4 r;
        r.x = w[0]  * a0.x + w[1]  * a0.y + w[2]  * a0.z + w[3]  * a0.w
            + w[4]  * a1.x + w[5]  * a1.y + w[6]  * a1.z + w[7]  * a1.w;
        r.y = w[8]  * a0.x + w[9]  * a0.y + w[10] * a0.z + w[11] * a0.w
            + w[12] * a1.x + w[13] * a1.y + w[14] * a1.z + w[15] * a1.w;
        r.z = w[16] * a0.x + w[17] * a0.y + w[18] * a0.z + w[19] * a0.w
            + w[20] * a1.x + w[21] * a1.y + w[22] * a1.z + w[23] * a1.w;
        r.w = w[24] * a0.x + w[25] * a0.y + w[26] * a0.z + w[27] * a0.w
            + w[28] * a1.x + w[29] * a1.y + w[30] * a1.z + w[31] * a1.w;
        *(float4*)&g_uhat[(((size_t)b * JJ + j) * II + i) * DD + dq * 4] = r;
    }
}

// ---------------------------------------------------------------------------
// One routing round, single pass over u_hat.
// Grid: (NCHUNK, B). CTA: 320 threads = 10 warps (warp = j), lane = il*4 + dq
//   (8 i-positions x 4 d-quads). Per iteration the warp reads a contiguous
//   512 B slab u[b,j, i0..i0+7, 0..15].
// logits bi[b,j,i] = dot(Osum[b,j,:], u[b,j,i,:]); c = softmax_j(bi);
// s[b,j,d] += c * u  (register accumulators, warp-reduced, atomicAdd at end).
__global__ __launch_bounds__(320)
void route_kernel() {
    const int chunk = blockIdx.x;
    const int b = blockIdx.y;
    const int tid = threadIdx.x;
    const int j = tid >> 5;          // warp id == output capsule
    const int lane = tid & 31;
    const int il = lane >> 2;        // 0..7
    const int dq = lane & 3;         // 0..3

    __shared__ float es[2][8][12];   // [buf][il][j] exp values (pad 12)

    float4 o4 = *(const float4*)&g_osum[(b * JJ + j) * DD + dq * 4];
    float acc0 = 0.f, acc1 = 0.f, acc2 = 0.f, acc3 = 0.f;

    const float* up = &g_uhat[(((size_t)b * JJ + j) * II + chunk * ICHUNK) * DD];

    int p = 0;
    for (int it = 0; it < ICHUNK / 8; it++) {
        const float4 u = *(const float4*)(up + (it * 8 + il) * DD + dq * 4);

        // partial logit over this thread's 4 dims, reduce across dq lanes
        float bi = u.x * o4.x + u.y * o4.y + u.z * o4.z + u.w * o4.w;
        bi += __shfl_xor_sync(0xffffffffu, bi, 1);
        bi += __shfl_xor_sync(0xffffffffu, bi, 2);

        // softmax over j (logits are tiny; no max-subtraction needed)
        float e = __expf(bi);
        if (dq == 0) es[p][il][j] = e;
        __syncthreads();
        const float* er = es[p][il];
        float4 e0 = *(const float4*)(er);
        float4 e1 = *(const float4*)(er + 4);
        float esum = e0.x + e0.y + e0.z + e0.w
                   + e1.x + e1.y + e1.z + e1.w + er[8] + er[9];
        float c = e / esum;

        acc0 += c * u.x; acc1 += c * u.y; acc2 += c * u.z; acc3 += c * u.w;
        p ^= 1;
    }

    // reduce accumulators over the 8 il-lanes (same dq)
#pragma unroll
    for (int m = 4; m < 32; m <<= 1) {
        acc0 += __shfl_xor_sync(0xffffffffu, acc0, m);
        acc1 += __shfl_xor_sync(0xffffffffu, acc1, m);
        acc2 += __shfl_xor_sync(0xffffffffu, acc2, m);
        acc3 += __shfl_xor_sync(0xffffffffu, acc3, m);
    }
    if (il == 0) {
        float* sp = &g_s[(b * JJ + j) * DD + dq * 4];
        atomicAdd(sp + 0, acc0);
        atomicAdd(sp + 1, acc1);
        atomicAdd(sp + 2, acc2);
        atomicAdd(sp + 3, acc3);
    }
}

// ---------------------------------------------------------------------------
// squash(s) ; if final: write d_out, else Osum += out and reset s for next round
__global__ void squash_kernel(float* __restrict__ out, int final_round) {
    int t = blockIdx.x * blockDim.x + threadIdx.x;   // (b*JJ + j)
    if (t >= BB * JJ) return;

    float4 v0 = *(const float4*)&g_s[t * DD + 0];
    float4 v1 = *(const float4*)&g_s[t * DD + 4];
    float4 v2 = *(const float4*)&g_s[t * DD + 8];
    float4 v3 = *(const float4*)&g_s[t * DD + 12];

    float ss = v0.x * v0.x + v0.y * v0.y + v0.z * v0.z + v0.w * v0.w
             + v1.x * v1.x + v1.y * v1.y + v1.z * v1.z + v1.w * v1.w
             + v2.x * v2.x + v2.y * v2.y + v2.z * v2.z + v2.w * v2.w
             + v3.x * v3.x + v3.y * v3.y + v3.z * v3.z + v3.w * v3.w;

    float scale = ss / (1.0f + ss) * rsqrtf(ss + 1e-7f);

    v0.x *= scale; v0.y *= scale; v0.z *= scale; v0.w *= scale;
    v1.x *= scale; v1.y *= scale; v1.z *= scale; v1.w *= scale;
    v2.x *= scale; v2.y *= scale; v2.z *= scale; v2.w *= scale;
    v3.x *= scale; v3.y *= scale; v3.z *= scale; v3.w *= scale;

    if (final_round) {
        *(float4*)&out[t * DD + 0]  = v0;
        *(float4*)&out[t * DD + 4]  = v1;
        *(float4*)&out[t * DD + 8]  = v2;
        *(float4*)&out[t * DD + 12] = v3;
    } else {
        float4 o0 = *(const float4*)&g_osum[t * DD + 0];
        float4 o1 = *(const float4*)&g_osum[t * DD + 4];
        float4 o2 = *(const float4*)&g_osum[t * DD + 8];
        float4 o3 = *(const float4*)&g_osum[t * DD + 12];
        o0.x += v0.x; o0.y += v0.y; o0.z += v0.z; o0.w += v0.w;
        o1.x += v1.x; o1.y += v1.y; o1.z += v1.z; o1.w += v1.w;
        o2.x += v2.x; o2.y += v2.y; o2.z += v2.z; o2.w += v2.w;
        o3.x += v3.x; o3.y += v3.y; o3.z += v3.z; o3.w += v3.w;
        *(float4*)&g_osum[t * DD + 0]  = o0;
        *(float4*)&g_osum[t * DD + 4]  = o1;
        *(float4*)&g_osum[t * DD + 8]  = o2;
        *(float4*)&g_osum[t * DD + 12] = o3;
        float4 z = make_float4(0.f, 0.f, 0.f, 0.f);
        *(float4*)&g_s[t * DD + 0]  = z;
        *(float4*)&g_s[t * DD + 4]  = z;
        *(float4*)&g_s[t * DD + 8]  = z;
        *(float4*)&g_s[t * DD + 12] = z;
    }
}

// ---------------------------------------------------------------------------
extern "C" void kernel_launch(void* const* d_in, const int* in_sizes, int n_in,
                              void* d_out, int out_size) {
    const float* inp = (const float*)d_in[0];
    const float* W   = (const float*)d_in[1];
    // guard against input-order surprises: sizes are distinct
    if (n_in >= 2 && in_sizes[0] == JJ * II * DD * KK) {
        const float* tmp = inp; inp = W; W = tmp;
    }
    float* out = (float*)d_out;

    init_kernel<<<(BB * JJ * DD + 255) / 256, 256>>>();
    uhat_kernel<<<II, 640>>>(inp, W);
    for (int r = 0; r < 3; r++) {
        route_kernel<<<dim3(NCHUNK, BB), 320>>>();
        squash_kernel<<<(BB * JJ + 255) / 256, 256>>>(out, r == 2 ? 1 : 0);
    }
}

// round 3
// speedup vs baseline: 1.7882x; 1.7882x over previous
#include <cuda_runtime.h>
#include <cuda_fp16.h>

// CapsuleLayer dynamic routing, GB300 sm_103a
// inputs: [B, I, K] fp32 ; W: [J, I, D, K] fp32 ; out: [B, J, D] fp32
#define BB 256
#define II 2048
#define KK 8
#define JJ 10
#define DD 16
#define NGROUPS ((II + 2) / 3)   // 683 groups of 3 i's (last has 2)
#define RCTA_X 4
#define RWARPS 8

// Scratch (device globals; no allocation allowed)
__device__ __half g_uhat[(size_t)BB * II * JJ * DD]; // [b][i][j][d] fp16, 168 MB
__device__ float g_s[BB * JJ * DD];
__device__ float g_osum[BB * JJ * DD];

// ---- f32x2 packed-FMA helpers (FFMA2 only reachable via PTX) -------------
static __device__ __forceinline__ unsigned long long pk2(float x, float y) {
    unsigned long long r;
    asm("mov.b64 %0, {%1, %2};" : "=l"(r) : "f"(x), "f"(y));
    return r;
}
static __device__ __forceinline__ void upk2(unsigned long long v, float& x, float& y) {
    asm("mov.b64 {%0, %1}, %2;" : "=f"(x), "=f"(y) : "l"(v));
}
static __device__ __forceinline__ unsigned long long fma2(
        unsigned long long a, unsigned long long b, unsigned long long c) {
    unsigned long long d;
    asm("fma.rn.f32x2 %0, %1, %2, %3;" : "=l"(d) : "l"(a), "l"(b), "l"(c));
    return d;
}

// ---------------------------------------------------------------------------
__global__ void init_kernel() {
    int t = blockIdx.x * blockDim.x + threadIdx.x;
    if (t < BB * JJ * DD) {
        g_s[t] = 0.0f;
        g_osum[t] = 0.0f;
    }
}

// ---------------------------------------------------------------------------
// u_hat[b,i,j,d] = sum_k W[j,i,d,k] * in[b,i,k]   (stored fp16)
// CTA per i. 640 threads = 16 bl x 10 j x 4 dq. W held in regs as f32x2 pairs.
__global__ __launch_bounds__(640, 2)
void uhat_kernel(const float* __restrict__ inp, const float* __restrict__ W) {
    const int i = blockIdx.x;
    __shared__ float in_s[BB][KK];   // 8 KB

    const int tid = threadIdx.x;
    for (int t = tid; t < (BB * KK) / 4; t += 640) {
        int b = t >> 1, kq = t & 1;
        *(float4*)&in_s[b][kq * 4] =
            *(const float4*)&inp[((size_t)b * II + i) * KK + kq * 4];
    }

    const int bl = tid / 40;
    const int rem = tid % 40;
    const int j = rem >> 2;
    const int dq = rem & 3;

    // W[j,i, dq*4 + {0,1,2,3}, k] packed as d-pairs for FFMA2
    unsigned long long p01[8], p23[8];
    {
        const float* wp = W + (((size_t)j * II + i) * DD + dq * 4) * KK;
        float w[32];
#pragma unroll
        for (int q = 0; q < 8; q++) {
            float4 v = *(const float4*)(wp + q * 4);
            w[q * 4 + 0] = v.x; w[q * 4 + 1] = v.y;
            w[q * 4 + 2] = v.z; w[q * 4 + 3] = v.w;
        }
#pragma unroll
        for (int k = 0; k < 8; k++) {
            p01[k] = pk2(w[k],      w[8 + k]);
            p23[k] = pk2(w[16 + k], w[24 + k]);
        }
    }
    __syncthreads();

#pragma unroll 2
    for (int bo = 0; bo < 16; bo++) {
        int b = bo * 16 + bl;
        float4 a0 = *(const float4*)&in_s[b][0];
        float4 a1 = *(const float4*)&in_s[b][4];
        float a[8] = {a0.x, a0.y, a0.z, a0.w, a1.x, a1.y, a1.z, a1.w};

        unsigned long long r01 = 0ull, r23 = 0ull;
#pragma unroll
        for (int k = 0; k < 8; k++) {
            unsigned long long aa = pk2(a[k], a[k]);
            r01 = fma2(p01[k], aa, r01);
            r23 = fma2(p23[k], aa, r23);
        }
        float rx, ry, rz, rw;
        upk2(r01, rx, ry);
        upk2(r23, rz, rw);

        __half2 h0 = __float22half2_rn(make_float2(rx, ry));
        __half2 h1 = __float22half2_rn(make_float2(rz, rw));
        uint2 st;
        st.x = *reinterpret_cast<unsigned int*>(&h0);
        st.y = *reinterpret_cast<unsigned int*>(&h1);
        *(uint2*)&g_uhat[(((size_t)b * II + i) * JJ + j) * DD + dq * 4] = st;
    }
}

// ---------------------------------------------------------------------------
// One routing round. Lane = (il in 0..2, j in 0..9); 30 active lanes; a lane
// owns the full 16-d vector u[b, i, j, :]. Softmax over j is 10 shfl_idx —
// no bar.sync, no smem in the inner loop. Double-buffered prefetch.
// Round 0 falls out naturally: osum=0 -> logits 0 -> uniform c.
__global__ __launch_bounds__(256)
void route_kernel() {
    const int b = blockIdx.y;
    const int tid = threadIdx.x;
    const int warp = tid >> 5;
    const int lane = tid & 31;
    const bool act = lane < 30;
    const int il = act ? lane / 10 : 2;
    const int j  = act ? lane % 10 : 0;
    const int il10 = il * 10;

    __shared__ float s_part[RWARPS][JJ][DD];   // 5 KB

    float os[16];
    {
        const float4* op = (const float4*)&g_osum[(b * JJ + j) * DD];
        float4 o0 = op[0], o1 = op[1], o2 = op[2], o3 = op[3];
        os[0] = o0.x; os[1] = o0.y; os[2]  = o0.z; os[3]  = o0.w;
        os[4] = o1.x; os[5] = o1.y; os[6]  = o1.z; os[7]  = o1.w;
        os[8] = o2.x; os[9] = o2.y; os[10] = o2.z; os[11] = o2.w;
        os[12] = o3.x; os[13] = o3.y; os[14] = o3.z; os[15] = o3.w;
    }

    float acc[16];
#pragma unroll
    for (int d = 0; d < 16; d++) acc[d] = 0.f;

    const int wg = blockIdx.x * RWARPS + warp;
    const int NW = gridDim.x * RWARPS;

    int g = wg;
    uint4 A0 = make_uint4(0, 0, 0, 0), A1 = make_uint4(0, 0, 0, 0);
    {
        int i = g * 3 + il;
        if (act && i < II) {
            const uint4* up = (const uint4*)(g_uhat + (((size_t)b * II + i) * JJ + j) * DD);
            A0 = up[0];
            A1 = up[1];
        }
    }

    while (g < NGROUPS) {
        const int gn = g + NW;
        uint4 B0 = make_uint4(0, 0, 0, 0), B1 = make_uint4(0, 0, 0, 0);
        {
            int i = gn * 3 + il;
            if (act && gn < NGROUPS && i < II) {
                const uint4* up = (const uint4*)(g_uhat + (((size_t)b * II + i) * JJ + j) * DD);
                B0 = up[0];
                B1 = up[1];
            }
        }

        float u[16];
        {
            const __half2* ha = (const __half2*)&A0;
#pragma unroll
            for (int q = 0; q < 4; q++) {
                float2 f = __half22float2(ha[q]);
                u[q * 2] = f.x; u[q * 2 + 1] = f.y;
            }
            const __half2* hb = (const __half2*)&A1;
#pragma unroll
            for (int q = 0; q < 4; q++) {
                float2 f = __half22float2(hb[q]);
                u[8 + q * 2] = f.x; u[8 + q * 2 + 1] = f.y;
            }
        }

        float lg = 0.f;
#pragma unroll
        for (int d = 0; d < 16; d++) lg = fmaf(os[d], u[d], lg);
        float e = __expf(lg);

        float esum = 0.f;
#pragma unroll
        for (int jj = 0; jj < 10; jj++)
            esum += __shfl_sync(0xffffffffu, e, il10 + jj);
        float c = __fdividef(e, esum);

#pragma unroll
        for (int d = 0; d < 16; d++) acc[d] = fmaf(c, u[d], acc[d]);

        A0 = B0; A1 = B1;
        g = gn;
    }

    // reduce the 3 il-groups: lanes 0..9 gather from lanes +10, +20
#pragma unroll
    for (int d = 0; d < 16; d++) {
        float v  = acc[d];
        float v1 = __shfl_sync(0xffffffffu, v, lane + 10);
        float v2 = __shfl_sync(0xffffffffu, v, lane + 20);
        v = v + v1 + v2;
        if (lane < 10) s_part[warp][lane][d] = v;
    }
    __syncthreads();

    if (tid < JJ * DD) {
        int jj = tid >> 4, d = tid & 15;
        float t = 0.f;
#pragma unroll
        for (int w = 0; w < RWARPS; w++) t += s_part[w][jj][d];
        atomicAdd(&g_s[(b * JJ + jj) * DD + d], t);
    }
}

// ---------------------------------------------------------------------------
__global__ void squash_kernel(float* __restrict__ out, int final_round) {
    int t = blockIdx.x * blockDim.x + threadIdx.x;   // (b*JJ + j)
    if (t >= BB * JJ) return;

    float4 v0 = *(const float4*)&g_s[t * DD + 0];
    float4 v1 = *(const float4*)&g_s[t * DD + 4];
    float4 v2 = *(const float4*)&g_s[t * DD + 8];
    float4 v3 = *(const float4*)&g_s[t * DD + 12];

    float ss = v0.x * v0.x + v0.y * v0.y + v0.z * v0.z + v0.w * v0.w
             + v1.x * v1.x + v1.y * v1.y + v1.z * v1.z + v1.w * v1.w
             + v2.x * v2.x + v2.y * v2.y + v2.z * v2.z + v2.w * v2.w
             + v3.x * v3.x + v3.y * v3.y + v3.z * v3.z + v3.w * v3.w;

    float scale = ss / (1.0f + ss) * rsqrtf(ss + 1e-7f);

    v0.x *= scale; v0.y *= scale; v0.z *= scale; v0.w *= scale;
    v1.x *= scale; v1.y *= scale; v1.z *= scale; v1.w *= scale;
    v2.x *= scale; v2.y *= scale; v2.z *= scale; v2.w *= scale;
    v3.x *= scale; v3.y *= scale; v3.z *= scale; v3.w *= scale;

    if (final_round) {
        *(float4*)&out[t * DD + 0]  = v0;
        *(float4*)&out[t * DD + 4]  = v1;
        *(float4*)&out[t * DD + 8]  = v2;
        *(float4*)&out[t * DD + 12] = v3;
    } else {
        float4 o0 = *(const float4*)&g_osum[t * DD + 0];
        float4 o1 = *(const float4*)&g_osum[t * DD + 4];
        float4 o2 = *(const float4*)&g_osum[t * DD + 8];
        float4 o3 = *(const float4*)&g_osum[t * DD + 12];
        o0.x += v0.x; o0.y += v0.y; o0.z += v0.z; o0.w += v0.w;
        o1.x += v1.x; o1.y += v1.y; o1.z += v1.z; o1.w += v1.w;
        o2.x += v2.x; o2.y += v2.y; o2.z += v2.z; o2.w += v2.w;
        o3.x += v3.x; o3.y += v3.y; o3.z += v3.z; o3.w += v3.w;
        *(float4*)&g_osum[t * DD + 0]  = o0;
        *(float4*)&g_osum[t * DD + 4]  = o1;
        *(float4*)&g_osum[t * DD + 8]  = o2;
        *(float4*)&g_osum[t * DD + 12] = o3;
        float4 z = make_float4(0.f, 0.f, 0.f, 0.f);
        *(float4*)&g_s[t * DD + 0]  = z;
        *(float4*)&g_s[t * DD + 4]  = z;
        *(float4*)&g_s[t * DD + 8]  = z;
        *(float4*)&g_s[t * DD + 12] = z;
    }
}

// ---------------------------------------------------------------------------
extern "C" void kernel_launch(void* const* d_in, const int* in_sizes, int n_in,
                              void* d_out, int out_size) {
    const float* inp = (const float*)d_in[0];
    const float* W   = (const float*)d_in[1];
    if (n_in >= 2 && in_sizes[0] == JJ * II * DD * KK) {
        const float* tmp = inp; inp = W; W = tmp;
    }
    float* out = (float*)d_out;

    init_kernel<<<(BB * JJ * DD + 255) / 256, 256>>>();
    uhat_kernel<<<II, 640>>>(inp, W);
    for (int r = 0; r < 3; r++) {
        route_kernel<<<dim3(RCTA_X, BB), 256>>>();
        squash_kernel<<<(BB * JJ + 255) / 256, 256>>>(out, r == 2 ? 1 : 0);
    }
}

// round 4
// speedup vs baseline: 1.8578x; 1.0389x over previous
#include <cuda_runtime.h>
#include <cuda_fp16.h>

// CapsuleLayer dynamic routing, GB300 sm_103a
// inputs: [B, I, K] fp32 ; W: [J, I, D, K] fp32 ; out: [B, J, D] fp32
#define BB 256
#define II 2048
#define KK 8
#define JJ 10
#define DD 16
#define IT 32            // i's per uhat CTA
#define BT 32            // b's per uhat CTA
#define NGROUPS ((II + 2) / 3)   // 683 groups of 3 i's
#define RCTA_X 8
#define RWARPS 8

// Scratch (device globals; no allocation allowed)
__device__ __half g_uhat[(size_t)BB * II * JJ * DD]; // [b][i][j][d] fp16, 168 MB
__device__ float g_s0[BB * JJ * DD];  // s from round 0 (fused, fp32-exact)
__device__ float g_s1[BB * JJ * DD];  // s from round 1
__device__ float g_s2[BB * JJ * DD];  // s from round 2

// ---- f32x2 packed-FMA helpers (FFMA2 only reachable via PTX) -------------
static __device__ __forceinline__ unsigned long long pk2(float x, float y) {
    unsigned long long r;
    asm("mov.b64 %0, {%1, %2};" : "=l"(r) : "f"(x), "f"(y));
    return r;
}
static __device__ __forceinline__ void upk2(unsigned long long v, float& x, float& y) {
    asm("mov.b64 {%0, %1}, %2;" : "=f"(x), "=f"(y) : "l"(v));
}
static __device__ __forceinline__ unsigned long long fma2(
        unsigned long long a, unsigned long long b, unsigned long long c) {
    unsigned long long d;
    asm("fma.rn.f32x2 %0, %1, %2, %3;" : "=l"(d) : "l"(a), "l"(b), "l"(c));
    return d;
}

// ---------------------------------------------------------------------------
__global__ void init_kernel() {
    int t = blockIdx.x * blockDim.x + threadIdx.x;
    if (t < BB * JJ * DD) {
        g_s0[t] = 0.0f;
        g_s1[t] = 0.0f;
        g_s2[t] = 0.0f;
    }
}

// ---------------------------------------------------------------------------
// u_hat[b,i,j,d] = sum_k W[j,i,d,k] * in[b,i,k]  (stored fp16)
// PLUS fused routing round 0: s0[b,j,d] = 0.1 * sum_i u_hat (fp32-exact).
// CTA = (i-chunk of 32, b-chunk of 32). 320 threads: bp = tid&7 (8 b-lanes,
// each covering 4 b's), jdq = tid>>3 (10 j x 4 dq). W and inputs staged via
// double-buffered smem; W held in regs as f32x2 pairs per i.
__global__ __launch_bounds__(320, 2)
void uhat_kernel(const float* __restrict__ inp, const float* __restrict__ W) {
    const int i0 = blockIdx.x * IT;
    const int b0 = blockIdx.y * BT;
    const int tid = threadIdx.x;
    const int bp = tid & 7;
    const int jdq = tid >> 3;       // 0..39
    const int j = jdq >> 2;
    const int dq = jdq & 3;

    __shared__ float w_s[2][1280];      // W[j, i, d, k] for one i: 10*16*8
    __shared__ float in_s[2][BT][12];   // inputs[b0..b0+31, i, 0..7] (pad 12)

    float sacc[16];
#pragma unroll
    for (int t = 0; t < 16; t++) sacc[t] = 0.f;

    // ---- stage i into buffer ----
    auto stage = [&](int buf, int i) {
        // W slab: 1280 floats = 320 float4, one per thread. W[j,i] = 128
        // contiguous floats.
        {
            int jj = tid >> 5;          // 0..9
            int r  = tid & 31;          // float4 index within 512B row
            float4 v = *(const float4*)(W + ((size_t)jj * II + i) * 128 + r * 4);
            *(float4*)&w_s[buf][jj * 128 + r * 4] = v;
        }
        // inputs: 64 float4 (threads 0..63): 32B per b (one sector each)
        if (tid < 64) {
            int b = tid >> 1, kq = tid & 1;
            float4 v = *(const float4*)(inp + ((size_t)(b0 + b) * II + i) * KK + kq * 4);
            *(float4*)&in_s[buf][b][kq * 4] = v;
        }
    };

    stage(0, i0);
    __syncthreads();
    int buf = 0;

    for (int ii = 0; ii < IT; ii++) {
        if (ii + 1 < IT) stage(buf ^ 1, i0 + ii + 1);
        const int i = i0 + ii;

        // W regs for this (j, dq): 32 floats -> 16 f32x2 pairs
        unsigned long long p01[8], p23[8];
        {
            const float* wb = &w_s[buf][j * 128 + dq * 32];
            float w[32];
#pragma unroll
            for (int q = 0; q < 8; q++) {
                float4 v = *(const float4*)(wb + q * 4);
                w[q * 4 + 0] = v.x; w[q * 4 + 1] = v.y;
                w[q * 4 + 2] = v.z; w[q * 4 + 3] = v.w;
            }
#pragma unroll
            for (int k = 0; k < 8; k++) {
                p01[k] = pk2(w[k],      w[8 + k]);
                p23[k] = pk2(w[16 + k], w[24 + k]);
            }
        }

#pragma unroll
        for (int bo = 0; bo < 4; bo++) {
            const int bl = bo * 8 + bp;
            float4 a0 = *(const float4*)&in_s[buf][bl][0];
            float4 a1 = *(const float4*)&in_s[buf][bl][4];
            float a[8] = {a0.x, a0.y, a0.z, a0.w, a1.x, a1.y, a1.z, a1.w};

            unsigned long long r01 = 0ull, r23 = 0ull;
#pragma unroll
            for (int k = 0; k < 8; k++) {
                unsigned long long aa = pk2(a[k], a[k]);
                r01 = fma2(p01[k], aa, r01);
                r23 = fma2(p23[k], aa, r23);
            }
            float rx, ry, rz, rw;
            upk2(r01, rx, ry);
            upk2(r23, rz, rw);

            __half2 h0 = __float22half2_rn(make_float2(rx, ry));
            __half2 h1 = __float22half2_rn(make_float2(rz, rw));
            uint2 st;
            st.x = *reinterpret_cast<unsigned int*>(&h0);
            st.y = *reinterpret_cast<unsigned int*>(&h1);
            *(uint2*)&g_uhat[(((size_t)(b0 + bl) * II + i) * JJ + j) * DD + dq * 4] = st;

            sacc[bo * 4 + 0] += rx;
            sacc[bo * 4 + 1] += ry;
            sacc[bo * 4 + 2] += rz;
            sacc[bo * 4 + 3] += rw;
        }
        __syncthreads();
        buf ^= 1;
    }

    // fused round 0: s0 += 0.1 * sum_i u
#pragma unroll
    for (int bo = 0; bo < 4; bo++) {
        const int b = b0 + bo * 8 + bp;
        float* sp = &g_s0[((size_t)b * JJ + j) * DD + dq * 4];
        atomicAdd(sp + 0, 0.1f * sacc[bo * 4 + 0]);
        atomicAdd(sp + 1, 0.1f * sacc[bo * 4 + 1]);
        atomicAdd(sp + 2, 0.1f * sacc[bo * 4 + 2]);
        atomicAdd(sp + 3, 0.1f * sacc[bo * 4 + 3]);
    }
}

// ---------------------------------------------------------------------------
static __device__ __forceinline__ void squash16_add(const float* __restrict__ s,
                                                    float* __restrict__ o) {
    float4 v0 = *(const float4*)(s + 0);
    float4 v1 = *(const float4*)(s + 4);
    float4 v2 = *(const float4*)(s + 8);
    float4 v3 = *(const float4*)(s + 12);
    float ss = v0.x * v0.x + v0.y * v0.y + v0.z * v0.z + v0.w * v0.w
             + v1.x * v1.x + v1.y * v1.y + v1.z * v1.z + v1.w * v1.w
             + v2.x * v2.x + v2.y * v2.y + v2.z * v2.z + v2.w * v2.w
             + v3.x * v3.x + v3.y * v3.y + v3.z * v3.z + v3.w * v3.w;
    float scale = ss / (1.0f + ss) * rsqrtf(ss + 1e-7f);
    o[0]  += scale * v0.x; o[1]  += scale * v0.y; o[2]  += scale * v0.z; o[3]  += scale * v0.w;
    o[4]  += scale * v1.x; o[5]  += scale * v1.y; o[6]  += scale * v1.z; o[7]  += scale * v1.w;
    o[8]  += scale * v2.x; o[9]  += scale * v2.y; o[10] += scale * v2.z; o[11] += scale * v2.w;
    o[12] += scale * v3.x; o[13] += scale * v3.y; o[14] += scale * v3.z; o[15] += scale * v3.w;
}

// ---------------------------------------------------------------------------
// One routing round (rounds 1 and 2). Lane = (il 0..2, j 0..9); a lane owns
// the full 16-d vector u[b,i,j,:]. osum is recomputed locally per thread from
// previous-round s buffers (squash of 160 floats — trivial). Softmax-over-j
// sum done with a 4-shfl log-depth tree. No bar.sync/smem in the inner loop.
__global__ __launch_bounds__(256)
void route_kernel(int round) {
    const int b = blockIdx.y;
    const int tid = threadIdx.x;
    const int warp = tid >> 5;
    const int lane = tid & 31;
    const bool act = lane < 30;
    const int il = act ? lane / 10 : 2;
    const int j  = act ? lane % 10 : 0;
    const int il10 = il * 10;
    const int jm = (j >= 5) ? j - 5 : j;

    __shared__ float s_part[RWARPS][JJ][DD];   // 5 KB

    // osum[b,j,:] = squash(s0) (+ squash(s1) if round 2)
    float os[16];
#pragma unroll
    for (int d = 0; d < 16; d++) os[d] = 0.f;
    squash16_add(&g_s0[(b * JJ + j) * DD], os);
    if (round == 2) squash16_add(&g_s1[(b * JJ + j) * DD], os);

    float* sOut = (round == 2) ? g_s2 : g_s1;

    float acc[16];
#pragma unroll
    for (int d = 0; d < 16; d++) acc[d] = 0.f;

    const int wg = blockIdx.x * RWARPS + warp;
    const int NW = RCTA_X * RWARPS;

    int g = wg;
    uint4 A0 = make_uint4(0, 0, 0, 0), A1 = make_uint4(0, 0, 0, 0);
    {
        int i = g * 3 + il;
        if (act && i < II) {
            const uint4* up = (const uint4*)(g_uhat + (((size_t)b * II + i) * JJ + j) * DD);
            A0 = up[0];
            A1 = up[1];
        }
    }

    while (g < NGROUPS) {
        const int gn = g + NW;
        uint4 B0 = make_uint4(0, 0, 0, 0), B1 = make_uint4(0, 0, 0, 0);
        {
            int i = gn * 3 + il;
            if (act && gn < NGROUPS && i < II) {
                const uint4* up = (const uint4*)(g_uhat + (((size_t)b * II + i) * JJ + j) * DD);
                B0 = up[0];
                B1 = up[1];
            }
        }

        float u[16];
        {
            const __half2* ha = (const __half2*)&A0;
#pragma unroll
            for (int q = 0; q < 4; q++) {
                float2 f = __half22float2(ha[q]);
                u[q * 2] = f.x; u[q * 2 + 1] = f.y;
            }
            const __half2* hb = (const __half2*)&A1;
#pragma unroll
            for (int q = 0; q < 4; q++) {
                float2 f = __half22float2(hb[q]);
                u[8 + q * 2] = f.x; u[8 + q * 2 + 1] = f.y;
            }
        }

        float lg = 0.f;
#pragma unroll
        for (int d = 0; d < 16; d++) lg = fmaf(os[d], u[d], lg);
        float e = __expf(lg);

        // esum over the 10 j's of this il-group: 4-shfl log-depth tree
        float ep = e + __shfl_sync(0xffffffffu, e, il10 + ((j + 5) % 10));
        float q1 = ep + __shfl_sync(0xffffffffu, ep, il10 + ((jm + 1) % 5));
        float e4 = __shfl_sync(0xffffffffu, ep, il10 + ((jm + 4) % 5));
        float q2 = q1 + __shfl_sync(0xffffffffu, q1, il10 + ((jm + 2) % 5));
        float esum = q2 + e4;
        float c = __fdividef(e, esum);

#pragma unroll
        for (int d = 0; d < 16; d++) acc[d] = fmaf(c, u[d], acc[d]);

        A0 = B0; A1 = B1;
        g = gn;
    }

    // reduce the 3 il-groups: lanes 0..9 gather from lanes +10, +20
#pragma unroll
    for (int d = 0; d < 16; d++) {
        float v  = acc[d];
        float v1 = __shfl_sync(0xffffffffu, v, lane + 10);
        float v2 = __shfl_sync(0xffffffffu, v, lane + 20);
        v = v + v1 + v2;
        if (lane < 10) s_part[warp][lane][d] = v;
    }
    __syncthreads();

    if (tid < JJ * DD) {
        int jj = tid >> 4, d = tid & 15;
        float t = 0.f;
#pragma unroll
        for (int w = 0; w < RWARPS; w++) t += s_part[w][jj][d];
        atomicAdd(&sOut[(b * JJ + jj) * DD + d], t);
    }
}

// ---------------------------------------------------------------------------
__global__ void squash_final_kernel(float* __restrict__ out) {
    int t = blockIdx.x * blockDim.x + threadIdx.x;   // (b*JJ + j)
    if (t >= BB * JJ) return;
    float o[16];
#pragma unroll
    for (int d = 0; d < 16; d++) o[d] = 0.f;
    squash16_add(&g_s2[t * DD], o);
#pragma unroll
    for (int q = 0; q < 4; q++) {
        float4 v = make_float4(o[q * 4], o[q * 4 + 1], o[q * 4 + 2], o[q * 4 + 3]);
        *(float4*)&out[t * DD + q * 4] = v;
    }
}

// ---------------------------------------------------------------------------
extern "C" void kernel_launch(void* const* d_in, const int* in_sizes, int n_in,
                              void* d_out, int out_size) {
    const float* inp = (const float*)d_in[0];
    const float* W   = (const float*)d_in[1];
    if (n_in >= 2 && in_sizes[0] == JJ * II * DD * KK) {
        const float* tmp = inp; inp = W; W = tmp;
    }
    float* out = (float*)d_out;

    init_kernel<<<(BB * JJ * DD + 255) / 256, 256>>>();
    uhat_kernel<<<dim3(II / IT, BB / BT), 320>>>(inp, W);
    route_kernel<<<dim3(RCTA_X, BB), 256>>>(1);
    route_kernel<<<dim3(RCTA_X, BB), 256>>>(2);
    squash_final_kernel<<<(BB * JJ + 255) / 256, 256>>>(out);
}